// round 10
// baseline (speedup 1.0000x reference)
#include <cuda_runtime.h>
#include <cuda_bf16.h>
#include <math.h>
#include <stdint.h>

#define T_    128
#define B_    1024
#define LAG_  6
#define H_    256
#define G_    1024            // 4*H
#define NR_   (T_*B_)         // 131072
#define BH_   (B_*H_)         // 262144

typedef __nv_bfloat16 bf16;

// ============================ device scratch ================================
__device__ float g_A0[(size_t)NR_*G_];          // input-gate precompute (L0)
__device__ float g_bufB[NR_*H_];                // f32 staging before out3
__device__ bf16 g_u_hi[NR_*H_],  g_u_lo[NR_*H_];
__device__ bf16 g_v_hi[NR_*H_],  g_v_lo[NR_*H_];
__device__ bf16 g_hsr_hi[NR_*H_], g_hsr_lo[NR_*H_];   // relu(h1) split, per t
__device__ bf16 g_h0_hi[2*BH_], g_h0_lo[2*BH_];
__device__ bf16 g_h1_hi[2*BH_], g_h1_lo[2*BH_];
__device__ float g_c0[2*BH_], g_c1[2*BH_];
// split weights (row-major [N][K])
__device__ bf16 g_Wi2_hi[H_*H_], g_Wi2_lo[H_*H_];
__device__ bf16 g_Wi3_hi[H_*H_], g_Wi3_lo[H_*H_];
__device__ bf16 g_Wo1_hi[H_*H_], g_Wo1_lo[H_*H_];
__device__ bf16 g_Wo2_hi[H_*H_], g_Wo2_lo[H_*H_];
__device__ bf16 g_Wih0_hi[G_*H_], g_Wih0_lo[G_*H_];   // gate-interleaved rows
__device__ bf16 g_Whh0_hi[G_*H_], g_Whh0_lo[G_*H_];
__device__ bf16 g_W1_hi[G_*2*H_], g_W1_lo[G_*2*H_];   // [1024][512] = [Wih1|Whh1]
__device__ float g_b0r[G_], g_b1r[G_];
// grid barrier state
__device__ int g_bar_count;
__device__ volatile int g_bar_gen;

// ======================= low-level helpers ==================================
__device__ __forceinline__ void split_store(bf16* hi, bf16* lo, size_t i, float v) {
    bf16 h = __float2bfloat16(v);
    hi[i] = h;
    lo[i] = __float2bfloat16(v - __bfloat162float(h));
}
__device__ __forceinline__ float sigm(float x) { return 1.f / (1.f + expf(-x)); }
__device__ __forceinline__ uint32_t smem_u32(const void* p) {
    uint32_t a;
    asm("{ .reg .u64 t; cvta.to.shared.u64 t, %1; cvt.u32.u64 %0, t; }" : "=r"(a) : "l"(p));
    return a;
}
__device__ __forceinline__ void cp16(uint32_t dst, const void* src) {
    asm volatile("cp.async.cg.shared.global [%0], [%1], 16;" :: "r"(dst), "l"(src));
}
__device__ __forceinline__ void cp_commit() { asm volatile("cp.async.commit_group;" ::: "memory"); }
__device__ __forceinline__ void cp_wait1()  { asm volatile("cp.async.wait_group 1;" ::: "memory"); }
__device__ __forceinline__ void cp_wait0()  { asm volatile("cp.async.wait_group 0;" ::: "memory"); }
__device__ __forceinline__ void ldm_x4(uint32_t* r, uint32_t addr) {
    asm volatile("ldmatrix.sync.aligned.m8n8.x4.shared.b16 {%0,%1,%2,%3}, [%4];"
                 : "=r"(r[0]), "=r"(r[1]), "=r"(r[2]), "=r"(r[3]) : "r"(addr));
}
__device__ __forceinline__ void mma16816(float* c, const uint32_t* a, const uint32_t* b) {
    asm volatile("mma.sync.aligned.m16n8k16.row.col.f32.bf16.bf16.f32 "
                 "{%0,%1,%2,%3}, {%4,%5,%6,%7}, {%8,%9}, {%0,%1,%2,%3};"
                 : "+f"(c[0]), "+f"(c[1]), "+f"(c[2]), "+f"(c[3])
                 : "r"(a[0]), "r"(a[1]), "r"(a[2]), "r"(a[3]), "r"(b[0]), "r"(b[1]));
}

#define CST_STR 132
// unified core (512 thr): BK=64 stages
#define ASTR2 72                   // 64 + 8 pad halves, 144 B row stride
#define MSZ2  18432                // one 128x64 bf16 matrix image
#define STG2  (4 * MSZ2)           // 73728 B per stage (Ah, Al, Wh, Wl)
#define RSMEM (3 * STG2)           // 221184, 3 stages, 1 CTA/SM
#define NCTA_STEP 128

// ===== unified GEMM core: 512 thr, BM=128, BN=128, BK=64, 3-stage ring ======
// C tile of [Aa|Ab](row-major, ld=H_) @ W^T; W row-major [N][K].
// Register double-buffered ldmatrix fragments across k16 steps.
struct Core512Args {
    const bf16 *Aa_hi, *Aa_lo, *Ab_hi, *Ab_lo, *W_hi, *W_lo;
    int K;      // 256 or 512
};

__device__ __forceinline__ void gemm_core512(const Core512Args& g, char* smbuf,
                                             int bm, int bn, float acc[2][4][4]) {
    int tid = threadIdx.x, lane = tid & 31, wid = tid >> 5;
    int wm = wid >> 2, wn = wid & 3;             // 4x4 warp grid, tile 32x32
    uint32_t sb0 = smem_u32(smbuf);
    int n = g.K >> 6;                            // chunks of 64
    int r0 = tid >> 3, cg8 = (tid & 7) << 3;     // 64 rows x 64 cols per pass
    uint32_t so  = (uint32_t)(r0 * ASTR2 + cg8) * 2;
    uint32_t so2 = so + 64 * ASTR2 * 2;

    // fragment offsets within a stage (precomputed, stage-relative)
    uint32_t offB0, offB1, offA0, offA1;
    {
        int rowb0 = wn * 32 + ((lane >> 4) & 1) * 8 + (lane & 7);
        int colb  = ((lane >> 3) & 1) * 8;
        offB0 = (uint32_t)(rowb0 * ASTR2 + colb) * 2;
        offB1 = (uint32_t)((rowb0 + 16) * ASTR2 + colb) * 2;
        int rowa = wm * 32 + (lane & 7) + ((lane >> 3) & 1) * 8;
        int cola = ((lane >> 4) & 1) * 8;
        offA0 = (uint32_t)(rowa * ASTR2 + cola) * 2;
        offA1 = (uint32_t)((rowa + 16) * ASTR2 + cola) * 2;
    }

    auto load_chunk = [&](int c, int stage) {
        uint32_t sb = sb0 + stage * STG2;
        int k0 = c << 6;
        const bf16 *ph, *pl; int gk;
        if (k0 < H_) { ph = g.Aa_hi; pl = g.Aa_lo; gk = k0; }
        else         { ph = g.Ab_hi; pl = g.Ab_lo; gk = k0 - H_; }
        size_t ga = (size_t)(bm * 128 + r0) * H_ + gk + cg8;
        cp16(sb + so,              ph + ga);
        cp16(sb + MSZ2 + so,       pl + ga);
        cp16(sb + so2,             ph + ga + 64 * H_);
        cp16(sb + MSZ2 + so2,      pl + ga + 64 * H_);
        size_t gw = (size_t)(bn * 128 + r0) * g.K + k0 + cg8;
        cp16(sb + 2 * MSZ2 + so,   g.W_hi + gw);
        cp16(sb + 3 * MSZ2 + so,   g.W_lo + gw);
        cp16(sb + 2 * MSZ2 + so2,  g.W_hi + gw + (size_t)64 * g.K);
        cp16(sb + 3 * MSZ2 + so2,  g.W_lo + gw + (size_t)64 * g.K);
    };

    // frag buffers: cb = [bh0..7 | bl0..7], ca = [ah0 al0 ah1 al1] (4 each)
    uint32_t cb[2][16], ca[2][16];

    auto load_frags = [&](uint32_t sb, int k16, int buf) {
        uint32_t kc = (uint32_t)(k16 * 16) * 2;
        ldm_x4(cb[buf],      sb + 2 * MSZ2 + offB0 + kc);
        ldm_x4(cb[buf] + 4,  sb + 2 * MSZ2 + offB1 + kc);
        ldm_x4(cb[buf] + 8,  sb + 3 * MSZ2 + offB0 + kc);
        ldm_x4(cb[buf] + 12, sb + 3 * MSZ2 + offB1 + kc);
        ldm_x4(ca[buf],      sb + offA0 + kc);
        ldm_x4(ca[buf] + 4,  sb + MSZ2 + offA0 + kc);
        ldm_x4(ca[buf] + 8,  sb + offA1 + kc);
        ldm_x4(ca[buf] + 12, sb + MSZ2 + offA1 + kc);
    };

    auto mma_all = [&](int buf) {
#pragma unroll
        for (int mt = 0; mt < 2; mt++) {
            uint32_t* ah = ca[buf] + mt * 8;
            uint32_t* al = ah + 4;
#pragma unroll
            for (int nt = 0; nt < 4; nt++) {
                uint32_t* bh = cb[buf] + nt * 2;
                uint32_t* bl = bh + 8;
                mma16816(acc[mt][nt], ah, bh);
                mma16816(acc[mt][nt], ah, bl);
                mma16816(acc[mt][nt], al, bh);
            }
        }
    };

    load_chunk(0, 0); cp_commit();
    if (n > 1) load_chunk(1, 1);
    cp_commit();
    for (int i = 0; i < n; i++) {
        cp_wait1();
        __syncthreads();
        // safe with 3 stages: (i+2)%3 == (i-1)%3, whose compute finished
        if (i + 2 < n) load_chunk(i + 2, (i + 2) % 3);
        cp_commit();
        uint32_t sb = sb0 + (i % 3) * STG2;
        load_frags(sb, 0, 0);
#pragma unroll
        for (int k16 = 0; k16 < 4; k16++) {
            if (k16 < 3) load_frags(sb, k16 + 1, (k16 + 1) & 1);
            mma_all(k16 & 1);
        }
    }
    cp_wait0();
    __syncthreads();
}

__device__ __forceinline__ void stage_C512(float* Cst, const float acc[2][4][4],
                                           int wm, int wn, int lane) {
#pragma unroll
    for (int mt = 0; mt < 2; mt++)
#pragma unroll
        for (int nt = 0; nt < 4; nt++) {
            int r0 = wm * 32 + mt * 16 + (lane >> 2);
            int c0 = wn * 32 + nt * 8 + (lane & 3) * 2;
            Cst[r0 * CST_STR + c0]           = acc[mt][nt][0];
            Cst[r0 * CST_STR + c0 + 1]       = acc[mt][nt][1];
            Cst[(r0 + 8) * CST_STR + c0]     = acc[mt][nt][2];
            Cst[(r0 + 8) * CST_STR + c0 + 1] = acc[mt][nt][3];
        }
}

// ================= generic pipelined GEMM kernel (MLP / A0) =================
// MODE 0: out_f32 = D + bias ; MODE 3: relu split bf16 ; MODE 4: relu f32
template<int MODE>
__global__ void __launch_bounds__(512, 1)
wm_gemm(const bf16* __restrict__ A_hi, const bf16* __restrict__ A_lo,
        const bf16* __restrict__ W_hi, const bf16* __restrict__ W_lo,
        const float* __restrict__ bias,
        bf16* __restrict__ o_hi, bf16* __restrict__ o_lo,
        float* __restrict__ out_f32, int ldc) {
    extern __shared__ __align__(16) char smbuf[];
    int tid = threadIdx.x, lane = tid & 31, wid = tid >> 5;
    int wm = wid >> 2, wn = wid & 3;
    int bn = blockIdx.x, bm = blockIdx.y;

    float acc[2][4][4] = {};
    Core512Args g{A_hi, A_lo, A_hi, A_lo, W_hi, W_lo, H_};
    gemm_core512(g, smbuf, bm, bn, acc);

    float* Cst = (float*)smbuf;
    stage_C512(Cst, acc, wm, wn, lane);
    __syncthreads();

    int grow0 = bm * 128, gcol0 = bn * 128;
    int row = tid >> 2, q = tid & 3;
    const float* crow = Cst + row * CST_STR + q * 32;
    const float* brow = bias + gcol0 + q * 32;

    if (MODE == 0 || MODE == 4) {
        float* orow = out_f32 + (size_t)(grow0 + row) * ldc + gcol0 + q * 32;
#pragma unroll
        for (int j = 0; j < 32; j += 4) {
            float4 v;
            v.x = crow[j + 0] + brow[j + 0];
            v.y = crow[j + 1] + brow[j + 1];
            v.z = crow[j + 2] + brow[j + 2];
            v.w = crow[j + 3] + brow[j + 3];
            if (MODE == 4) {
                v.x = fmaxf(v.x, 0.f); v.y = fmaxf(v.y, 0.f);
                v.z = fmaxf(v.z, 0.f); v.w = fmaxf(v.w, 0.f);
            }
            *(float4*)(orow + j) = v;
        }
    } else {  // MODE 3
        size_t obase = (size_t)(grow0 + row) * ldc + gcol0 + q * 32;
#pragma unroll
        for (int j0 = 0; j0 < 32; j0 += 8) {
            bf16 vh[8], vl[8];
#pragma unroll
            for (int j = 0; j < 8; j++) {
                float v = fmaxf(crow[j0 + j] + brow[j0 + j], 0.f);
                bf16 h = __float2bfloat16(v);
                vh[j] = h;
                vl[j] = __float2bfloat16(v - __bfloat162float(h));
            }
            *(uint4*)(o_hi + obase + j0) = *(uint4*)vh;
            *(uint4*)(o_lo + obase + j0) = *(uint4*)vl;
        }
    }
}

// ================== persistent recurrence kernel ============================
__device__ __forceinline__ void grid_barrier() {
    __syncthreads();
    if (threadIdx.x == 0) {
        __threadfence();
        int gen = g_bar_gen;
        if (atomicAdd(&g_bar_count, 1) == NCTA_STEP - 1) {
            g_bar_count = 0;
            __threadfence();
            g_bar_gen = gen + 1;
        } else {
            while (g_bar_gen == gen) { }
        }
        __threadfence();
    }
    __syncthreads();
}

// roles: 0 = L0(s) gates (K=256); 1 = L1(s-1) gates (K=512 concat)
__global__ void __launch_bounds__(512, 1)
k_rnn() {
    extern __shared__ __align__(16) char smbuf[];
    int tid = threadIdx.x, lane = tid & 31, wid = tid >> 5;
    int wm = wid >> 2, wn = wid & 3;
    int role = blockIdx.x >> 6;          // 64 CTAs per role
    int tile = blockIdx.x & 63;
    int bn = tile & 7, bm = tile >> 3;   // 8 x 8 tiles of 128x128
    float* Cst = (float*)smbuf;

    for (int s = 0; s <= T_; s++) {
        int t = role ? (s - 1) : s;
        bool active = role ? (s >= 1) : (s < T_);
        if (active) {
            int r = t & 1, w = 1 - r;
            Core512Args g;
            const float *addend, *bias, *c_prev;
            float *c_new;
            bf16 *o_hi, *o_lo, *hr_hi = nullptr, *hr_lo = nullptr;
            if (role == 0) {
                g = {g_h0_hi + r * BH_, g_h0_lo + r * BH_,
                     g_h0_hi + r * BH_, g_h0_lo + r * BH_,
                     g_Whh0_hi, g_Whh0_lo, H_};
                addend = g_A0 + (size_t)t * B_ * G_;  bias = nullptr;
                c_prev = g_c0 + r * BH_; c_new = g_c0 + w * BH_;
                o_hi = g_h0_hi + w * BH_; o_lo = g_h0_lo + w * BH_;
            } else {
                g = {g_h0_hi + w * BH_, g_h0_lo + w * BH_,   // h0(t) in slot 1-(t&1)
                     g_h1_hi + r * BH_, g_h1_lo + r * BH_,
                     g_W1_hi, g_W1_lo, 2 * H_};
                addend = nullptr;  bias = g_b1r;
                c_prev = g_c1 + r * BH_; c_new = g_c1 + w * BH_;
                o_hi = g_h1_hi + w * BH_; o_lo = g_h1_lo + w * BH_;
                hr_hi = g_hsr_hi + (size_t)t * BH_; hr_lo = g_hsr_lo + (size_t)t * BH_;
            }

            float acc[2][4][4] = {};
            gemm_core512(g, smbuf, bm, bn, acc);
            stage_C512(Cst, acc, wm, wn, lane);
            __syncthreads();

            // LSTM cell epilogue: 512 threads, each 8 units of one row
            int grow0 = bm * 128, gcol0 = bn * 128;
            int row = tid >> 2, q = tid & 3;
#pragma unroll
            for (int u8 = 0; u8 < 8; u8++) {
                int ul = q * 8 + u8;
                float gg[4];
                const float* cp = Cst + row * CST_STR + ul * 4;
                if (role == 0) {
                    float4 ad = *(const float4*)(addend + (size_t)(grow0 + row) * G_ + gcol0 + ul * 4);
                    gg[0] = cp[0] + ad.x; gg[1] = cp[1] + ad.y;
                    gg[2] = cp[2] + ad.z; gg[3] = cp[3] + ad.w;
                } else {
                    const float* br = bias + gcol0 + ul * 4;
                    gg[0] = cp[0] + br[0]; gg[1] = cp[1] + br[1];
                    gg[2] = cp[2] + br[2]; gg[3] = cp[3] + br[3];
                }
                size_t ci = (size_t)(grow0 + row) * H_ + (gcol0 >> 2) + ul;
                float c = fmaf(sigm(gg[1]), c_prev[ci], sigm(gg[0]) * tanhf(gg[2]));
                c_new[ci] = c;
                float h = sigm(gg[3]) * tanhf(c);
                split_store(o_hi, o_lo, ci, h);
                if (hr_hi) split_store(hr_hi, hr_lo, ci, fmaxf(h, 0.f));
            }
        }
        if (s < T_) grid_barrier();
    }
}

// ======================= prep: split + gate reorder =========================
__global__ void k_prep(const float* __restrict__ Wi2, const float* __restrict__ Wi3,
                       const float* __restrict__ Wo1, const float* __restrict__ Wo2,
                       const float* __restrict__ Wih0, const float* __restrict__ Whh0,
                       const float* __restrict__ bih0, const float* __restrict__ bhh0,
                       const float* __restrict__ Wih1, const float* __restrict__ Whh1,
                       const float* __restrict__ bih1, const float* __restrict__ bhh1) {
    int idx = blockIdx.x * blockDim.x + threadIdx.x;
    int stride = gridDim.x * blockDim.x;
    for (int i = idx; i < H_ * H_; i += stride) {
        split_store(g_Wi2_hi, g_Wi2_lo, i, Wi2[i]);
        split_store(g_Wi3_hi, g_Wi3_lo, i, Wi3[i]);
        split_store(g_Wo1_hi, g_Wo1_lo, i, Wo1[i]);
        split_store(g_Wo2_hi, g_Wo2_lo, i, Wo2[i]);
    }
    for (int i = idx; i < G_ * H_; i += stride) {
        int rr = i / H_, k = i - rr * H_;
        int j = rr >> 2, gg = rr & 3;
        int src = (gg * H_ + j) * H_ + k;
        split_store(g_Wih0_hi, g_Wih0_lo, i, Wih0[src]);
        split_store(g_Whh0_hi, g_Whh0_lo, i, Whh0[src]);
    }
    for (int i = idx; i < G_ * 2 * H_; i += stride) {
        int rr = i / (2 * H_), k = i - rr * (2 * H_);
        int j = rr >> 2, gg = rr & 3;
        float v = (k < H_) ? Wih1[(gg * H_ + j) * H_ + k]
                           : Whh1[(gg * H_ + j) * H_ + (k - H_)];
        split_store(g_W1_hi, g_W1_lo, i, v);
    }
    if (idx < G_) {
        int j = idx >> 2, gg = idx & 3;
        g_b0r[idx] = bih0[gg * H_ + j] + bhh0[gg * H_ + j];
        g_b1r[idx] = bih1[gg * H_ + j] + bhh1[gg * H_ + j];
    }
    if (idx == 0) g_bar_count = 0;
}

__global__ void k_zero() {
    int idx = blockIdx.x * blockDim.x + threadIdx.x;
    int stride = gridDim.x * blockDim.x;
    for (int i = idx; i < 2 * BH_; i += stride) {
        g_h0_hi[i] = bf16(0.f); g_h0_lo[i] = bf16(0.f);
        g_h1_hi[i] = bf16(0.f); g_h1_lo[i] = bf16(0.f);
        g_c0[i] = 0.f; g_c1[i] = 0.f;
    }
}

// ===================== input MLP stage 1 (K=6) ==============================
__global__ void __launch_bounds__(256)
k_in1(const float* __restrict__ x, const float* __restrict__ Wi1,
      const float* __restrict__ bi1) {
    __shared__ float Ws[H_ * LAG_];
    __shared__ float bs[H_];
    int tid = threadIdx.x;
    for (int i = tid; i < H_ * LAG_; i += 256) Ws[i] = Wi1[i];
    if (tid < H_) bs[tid] = bi1[tid];
    __syncthreads();
    int j = tid;
    for (int rr = 0; rr < 64; rr++) {
        int row = blockIdx.x * 64 + rr;
        const float* xr = x + (size_t)row * LAG_;
        float acc = bs[j];
#pragma unroll
        for (int k = 0; k < LAG_; k++) acc = fmaf(xr[k], Ws[j * LAG_ + k], acc);
        split_store(g_u_hi, g_u_lo, (size_t)row * H_ + j, fmaxf(acc, 0.f));
    }
}

// ===================== output head (N=6) ====================================
__global__ void __launch_bounds__(256)
k_out3(const float* __restrict__ Ain, const float* __restrict__ Wo3,
       const float* __restrict__ bo3, float* __restrict__ y) {
    __shared__ float Ws[LAG_ * H_];
    int tid = threadIdx.x;
    for (int i = tid; i < LAG_ * H_; i += 256) Ws[i] = Wo3[i];
    __syncthreads();
    int wrp = tid >> 5, lane = tid & 31;
    int row = blockIdx.x * 8 + wrp;
    const float* ar = Ain + (size_t)row * H_;
    float acc[LAG_] = {};
    for (int k = lane; k < H_; k += 32) {
        float a = ar[k];
#pragma unroll
        for (int o = 0; o < LAG_; o++) acc[o] = fmaf(a, Ws[o * H_ + k], acc[o]);
    }
#pragma unroll
    for (int o = 0; o < LAG_; o++) {
        float v = acc[o];
#pragma unroll
        for (int off = 16; off; off >>= 1) v += __shfl_xor_sync(0xffffffffu, v, off);
        if (lane == 0) y[(size_t)row * LAG_ + o] = v + bo3[o];
    }
}

// ============================== host ========================================
extern "C" void kernel_launch(void* const* d_in, const int* in_sizes, int n_in,
                              void* d_out, int out_size) {
    const float* x    = (const float*)d_in[0];
    const float* Wi1  = (const float*)d_in[1];  const float* bi1 = (const float*)d_in[2];
    const float* Wi2  = (const float*)d_in[3];  const float* bi2 = (const float*)d_in[4];
    const float* Wi3  = (const float*)d_in[5];  const float* bi3 = (const float*)d_in[6];
    const float* Wih0 = (const float*)d_in[7];  const float* Whh0 = (const float*)d_in[8];
    const float* bih0 = (const float*)d_in[9];  const float* bhh0 = (const float*)d_in[10];
    const float* Wih1 = (const float*)d_in[11]; const float* Whh1 = (const float*)d_in[12];
    const float* bih1 = (const float*)d_in[13]; const float* bhh1 = (const float*)d_in[14];
    const float* Wo1  = (const float*)d_in[15]; const float* bo1 = (const float*)d_in[16];
    const float* Wo2  = (const float*)d_in[17]; const float* bo2 = (const float*)d_in[18];
    const float* Wo3  = (const float*)d_in[19]; const float* bo3 = (const float*)d_in[20];
    float* y = (float*)d_out;

    cudaFuncSetAttribute(wm_gemm<0>, cudaFuncAttributeMaxDynamicSharedMemorySize, RSMEM);
    cudaFuncSetAttribute(wm_gemm<3>, cudaFuncAttributeMaxDynamicSharedMemorySize, RSMEM);
    cudaFuncSetAttribute(wm_gemm<4>, cudaFuncAttributeMaxDynamicSharedMemorySize, RSMEM);
    cudaFuncSetAttribute(k_rnn,      cudaFuncAttributeMaxDynamicSharedMemorySize, RSMEM);

    float *A0, *bufB, *b0r;
    bf16 *u_hi, *u_lo, *v_hi, *v_lo, *hsr_hi, *hsr_lo;
    bf16 *Wi2h, *Wi2l, *Wi3h, *Wi3l, *Wo1h, *Wo1l, *Wo2h, *Wo2l, *Wih0h, *Wih0l;
    cudaGetSymbolAddress((void**)&A0,   g_A0);
    cudaGetSymbolAddress((void**)&bufB, g_bufB);
    cudaGetSymbolAddress((void**)&b0r,  g_b0r);
    cudaGetSymbolAddress((void**)&u_hi, g_u_hi);   cudaGetSymbolAddress((void**)&u_lo, g_u_lo);
    cudaGetSymbolAddress((void**)&v_hi, g_v_hi);   cudaGetSymbolAddress((void**)&v_lo, g_v_lo);
    cudaGetSymbolAddress((void**)&hsr_hi, g_hsr_hi); cudaGetSymbolAddress((void**)&hsr_lo, g_hsr_lo);
    cudaGetSymbolAddress((void**)&Wi2h, g_Wi2_hi); cudaGetSymbolAddress((void**)&Wi2l, g_Wi2_lo);
    cudaGetSymbolAddress((void**)&Wi3h, g_Wi3_hi); cudaGetSymbolAddress((void**)&Wi3l, g_Wi3_lo);
    cudaGetSymbolAddress((void**)&Wo1h, g_Wo1_hi); cudaGetSymbolAddress((void**)&Wo1l, g_Wo1_lo);
    cudaGetSymbolAddress((void**)&Wo2h, g_Wo2_hi); cudaGetSymbolAddress((void**)&Wo2l, g_Wo2_lo);
    cudaGetSymbolAddress((void**)&Wih0h, g_Wih0_hi); cudaGetSymbolAddress((void**)&Wih0l, g_Wih0_lo);

    k_prep<<<512, 512>>>(Wi2, Wi3, Wo1, Wo2, Wih0, Whh0, bih0, bhh0,
                         Wih1, Whh1, bih1, bhh1);
    k_zero<<<512, 512>>>();

    // input MLP
    k_in1<<<NR_ / 64, 256>>>(x, Wi1, bi1);
    dim3 gMLP(H_ / 128, NR_ / 128);              // (2, 1024)
    wm_gemm<3><<<gMLP, 512, RSMEM>>>(u_hi, u_lo, Wi2h, Wi2l, bi2,
                                     v_hi, v_lo, nullptr, H_);
    wm_gemm<3><<<gMLP, 512, RSMEM>>>(v_hi, v_lo, Wi3h, Wi3l, bi3,
                                     u_hi, u_lo, nullptr, H_);

    // hoisted layer-0 input projection: A0 = u @ Wih0r^T + b0r
    dim3 gA0(G_ / 128, NR_ / 128);               // (8, 1024)
    wm_gemm<0><<<gA0, 512, RSMEM>>>(u_hi, u_lo, Wih0h, Wih0l, b0r,
                                    nullptr, nullptr, A0, G_);

    // persistent 2-role recurrence: 128 CTAs x 512 threads, all SM-resident
    k_rnn<<<NCTA_STEP, 512, RSMEM>>>();

    // output MLP
    wm_gemm<3><<<gMLP, 512, RSMEM>>>(hsr_hi, hsr_lo, Wo1h, Wo1l, bo1,
                                     v_hi, v_lo, nullptr, H_);
    wm_gemm<4><<<gMLP, 512, RSMEM>>>(v_hi, v_lo, Wo2h, Wo2l, bo2,
                                     nullptr, nullptr, bufB, H_);
    k_out3<<<NR_ / 8, 256>>>(bufB, Wo3, bo3, y);
}

// round 11
// speedup vs baseline: 1.4088x; 1.4088x over previous
#include <cuda_runtime.h>
#include <cuda_fp16.h>
#include <math.h>
#include <stdint.h>

#define T_    128
#define B_    1024
#define LAG_  6
#define H_    256
#define G_    1024            // 4*H
#define NR_   (T_*B_)         // 131072
#define BH_   (B_*H_)         // 262144

typedef __half h16;

// ============================ device scratch ================================
__device__ float g_A0[(size_t)NR_*G_];          // input-gate precompute (L0)
__device__ float g_bufB[NR_*H_];                // f32 staging before out3
__device__ h16 g_u[NR_*H_];
__device__ h16 g_v[NR_*H_];
__device__ h16 g_hsr[NR_*H_];                   // relu(h1) per t
__device__ h16 g_h0[2*BH_];
__device__ h16 g_h1[2*BH_];
__device__ float g_c0[2*BH_], g_c1[2*BH_];
// split fp16 weights (row-major [N][K])
__device__ h16 g_Wi2_hi[H_*H_], g_Wi2_lo[H_*H_];
__device__ h16 g_Wi3_hi[H_*H_], g_Wi3_lo[H_*H_];
__device__ h16 g_Wo1_hi[H_*H_], g_Wo1_lo[H_*H_];
__device__ h16 g_Wo2_hi[H_*H_], g_Wo2_lo[H_*H_];
__device__ h16 g_Wih0_hi[G_*H_], g_Wih0_lo[G_*H_];   // gate-interleaved rows
__device__ h16 g_Whh0_hi[G_*H_], g_Whh0_lo[G_*H_];
__device__ h16 g_W1_hi[G_*2*H_], g_W1_lo[G_*2*H_];   // [1024][512] = [Wih1|Whh1]
__device__ float g_b0r[G_], g_b1r[G_];
// grid barrier state
__device__ int g_bar_count;
__device__ volatile int g_bar_gen;

// ======================= low-level helpers ==================================
__device__ __forceinline__ void wsplit(h16* hi, h16* lo, size_t i, float v) {
    h16 h = __float2half_rn(v);
    hi[i] = h;
    lo[i] = __float2half_rn(v - __half2float(h));
}
__device__ __forceinline__ float sigm(float x) { return 1.f / (1.f + expf(-x)); }
__device__ __forceinline__ uint32_t smem_u32(const void* p) {
    uint32_t a;
    asm("{ .reg .u64 t; cvta.to.shared.u64 t, %1; cvt.u32.u64 %0, t; }" : "=r"(a) : "l"(p));
    return a;
}
__device__ __forceinline__ void cp16(uint32_t dst, const void* src) {
    asm volatile("cp.async.cg.shared.global [%0], [%1], 16;" :: "r"(dst), "l"(src));
}
__device__ __forceinline__ void cp_commit() { asm volatile("cp.async.commit_group;" ::: "memory"); }
__device__ __forceinline__ void cp_wait1()  { asm volatile("cp.async.wait_group 1;" ::: "memory"); }
__device__ __forceinline__ void cp_wait0()  { asm volatile("cp.async.wait_group 0;" ::: "memory"); }
__device__ __forceinline__ void ldm_x4(uint32_t* r, uint32_t addr) {
    asm volatile("ldmatrix.sync.aligned.m8n8.x4.shared.b16 {%0,%1,%2,%3}, [%4];"
                 : "=r"(r[0]), "=r"(r[1]), "=r"(r[2]), "=r"(r[3]) : "r"(addr));
}
__device__ __forceinline__ void mma16816(float* c, const uint32_t* a, const uint32_t* b) {
    asm volatile("mma.sync.aligned.m16n8k16.row.col.f32.f16.f16.f32 "
                 "{%0,%1,%2,%3}, {%4,%5,%6,%7}, {%8,%9}, {%0,%1,%2,%3};"
                 : "+f"(c[0]), "+f"(c[1]), "+f"(c[2]), "+f"(c[3])
                 : "r"(a[0]), "r"(a[1]), "r"(a[2]), "r"(a[3]), "r"(b[0]), "r"(b[1]));
}

#define CST_STR 132
// MLP core (256 thr): stage = A[128][40] + Wh[128][40] + Wl[128][40]
#define ASTR  40
#define MSZ1  10240
#define STG1  (3 * MSZ1)           // 30720 per stage, 2 stages
#define SMEM_SZ 67584              // >= 2*STG1 (61440) and C staging (67584)
// recurrence core (512 thr): BK=64, stage = A + Wh + Wl (each 128x72 halves)
#define ASTR2 72
#define MSZ2  18432
#define STG2  (3 * MSZ2)           // 55296 per stage, 3 stages
#define RSMEM (3 * STG2)           // 165888, 1 CTA/SM
#define NCTA_STEP 128

// ============ MLP core (256 threads, BM=128, BN=128, K=256, 2-stage) ========
struct CoreArgs {
    const h16 *A, *W_hi, *W_lo;
};

__device__ __forceinline__ void gemm_core256(const CoreArgs& g, char* smbuf,
                                             int bm, int bn, float acc[4][4][4]) {
    int tid = threadIdx.x, lane = tid & 31, wid = tid >> 5;
    uint32_t sb0 = smem_u32(smbuf);
    int r0 = tid >> 2, cg8 = (tid & 3) << 3;
    uint32_t so  = (uint32_t)(r0 * ASTR + cg8) * 2;
    uint32_t so2 = so + 64 * ASTR * 2;
    int wm = wid >> 2, wn = wid & 3;

    auto load_chunk = [&](int c, int stage) {
        uint32_t sb = sb0 + stage * STG1;
        int k0 = c << 5;
        size_t ga = (size_t)(bm * 128 + r0) * H_ + k0 + cg8;
        cp16(sb + so,              g.A + ga);
        cp16(sb + so2,             g.A + ga + 64 * H_);
        size_t gw = (size_t)(bn * 128 + r0) * H_ + k0 + cg8;
        cp16(sb + MSZ1 + so,       g.W_hi + gw);
        cp16(sb + MSZ1 + so2,      g.W_hi + gw + 64 * H_);
        cp16(sb + 2 * MSZ1 + so,   g.W_lo + gw);
        cp16(sb + 2 * MSZ1 + so2,  g.W_lo + gw + 64 * H_);
    };

    auto compute_chunk = [&](int stage) {
        uint32_t sb = sb0 + stage * STG1;
#pragma unroll
        for (int k16 = 0; k16 < 2; k16++) {
            uint32_t bh[8], bl[8];
#pragma unroll
            for (int nt2 = 0; nt2 < 2; nt2++) {
                int row = wn * 32 + nt2 * 16 + ((lane >> 4) & 1) * 8 + (lane & 7);
                int colh = k16 * 16 + ((lane >> 3) & 1) * 8;
                uint32_t off = (uint32_t)(row * ASTR + colh) * 2;
                ldm_x4(bh + nt2 * 4, sb + MSZ1 + off);
                ldm_x4(bl + nt2 * 4, sb + 2 * MSZ1 + off);
            }
#pragma unroll
            for (int mt = 0; mt < 4; mt++) {
                int row = wm * 64 + mt * 16 + (lane & 7) + ((lane >> 3) & 1) * 8;
                int colh = k16 * 16 + ((lane >> 4) & 1) * 8;
                uint32_t off = (uint32_t)(row * ASTR + colh) * 2;
                uint32_t a[4];
                ldm_x4(a, sb + off);
#pragma unroll
                for (int nt = 0; nt < 4; nt++) {
                    mma16816(acc[mt][nt], a, bh + nt * 2);
                    mma16816(acc[mt][nt], a, bl + nt * 2);
                }
            }
        }
    };

    load_chunk(0, 0); cp_commit();
    load_chunk(1, 1); cp_commit();
    for (int i = 0; i < 8; i++) {
        cp_wait1();
        __syncthreads();
        compute_chunk(i & 1);
        __syncthreads();
        if (i + 2 < 8) load_chunk(i + 2, i & 1);
        cp_commit();
    }
    cp_wait0();
    __syncthreads();
}

// ================= generic pipelined GEMM kernel (MLP / A0) =================
// MODE 0: out_f32 = D + bias ; MODE 3: relu fp16 ; MODE 4: relu f32
template<int MODE>
__global__ void __launch_bounds__(256, 2)
wm_gemm(const h16* __restrict__ A, const h16* __restrict__ W_hi,
        const h16* __restrict__ W_lo, const float* __restrict__ bias,
        h16* __restrict__ o_h, float* __restrict__ out_f32, int ldc) {
    extern __shared__ __align__(16) char smbuf[];
    int tid = threadIdx.x, lane = tid & 31, wid = tid >> 5;
    int wm = wid >> 2, wn = wid & 3;
    int bn = blockIdx.x, bm = blockIdx.y;

    float acc[4][4][4] = {};
    CoreArgs g{A, W_hi, W_lo};
    gemm_core256(g, smbuf, bm, bn, acc);

    float* Cst = (float*)smbuf;
#pragma unroll
    for (int mt = 0; mt < 4; mt++)
#pragma unroll
        for (int nt = 0; nt < 4; nt++) {
            int r0 = wm * 64 + mt * 16 + (lane >> 2);
            int c0 = wn * 32 + nt * 8 + (lane & 3) * 2;
            Cst[r0 * CST_STR + c0]           = acc[mt][nt][0];
            Cst[r0 * CST_STR + c0 + 1]       = acc[mt][nt][1];
            Cst[(r0 + 8) * CST_STR + c0]     = acc[mt][nt][2];
            Cst[(r0 + 8) * CST_STR + c0 + 1] = acc[mt][nt][3];
        }
    __syncthreads();

    int grow0 = bm * 128, gcol0 = bn * 128;
    int row = tid >> 1, half = tid & 1;
    const float* crow = Cst + row * CST_STR + half * 64;
    const float* brow = bias + gcol0 + half * 64;

    if (MODE == 0 || MODE == 4) {
        float* orow = out_f32 + (size_t)(grow0 + row) * ldc + gcol0 + half * 64;
#pragma unroll
        for (int j = 0; j < 64; j += 4) {
            float4 v;
            v.x = crow[j + 0] + brow[j + 0];
            v.y = crow[j + 1] + brow[j + 1];
            v.z = crow[j + 2] + brow[j + 2];
            v.w = crow[j + 3] + brow[j + 3];
            if (MODE == 4) {
                v.x = fmaxf(v.x, 0.f); v.y = fmaxf(v.y, 0.f);
                v.z = fmaxf(v.z, 0.f); v.w = fmaxf(v.w, 0.f);
            }
            *(float4*)(orow + j) = v;
        }
    } else {  // MODE 3: relu -> fp16
        size_t obase = (size_t)(grow0 + row) * ldc + gcol0 + half * 64;
#pragma unroll
        for (int j0 = 0; j0 < 64; j0 += 8) {
            h16 vh[8];
#pragma unroll
            for (int j = 0; j < 8; j++)
                vh[j] = __float2half_rn(fmaxf(crow[j0 + j] + brow[j0 + j], 0.f));
            *(uint4*)(o_h + obase + j0) = *(uint4*)vh;
        }
    }
}

// ===== recurrence core (512 threads, BM=128, BN=128, BK=64, 3-stage) ========
struct Core512Args {
    const h16 *Aa, *Ab, *W_hi, *W_lo;
    int K;      // 256 or 512; W row stride = K; A sources each [rows][256]
};

__device__ __forceinline__ void gemm_core512(const Core512Args& g, char* smbuf,
                                             int bm, int bn, float acc[2][4][4]) {
    int tid = threadIdx.x, lane = tid & 31, wid = tid >> 5;
    int wm = wid >> 2, wn = wid & 3;             // 4x4 warp grid, tile 32x32
    uint32_t sb0 = smem_u32(smbuf);
    int n = g.K >> 6;                            // chunks of 64
    int r0 = tid >> 3, cg8 = (tid & 7) << 3;     // 64 rows x 64 cols per pass
    uint32_t so  = (uint32_t)(r0 * ASTR2 + cg8) * 2;
    uint32_t so2 = so + 64 * ASTR2 * 2;

    auto load_chunk = [&](int c, int stage) {
        uint32_t sb = sb0 + stage * STG2;
        int k0 = c << 6;
        const h16* pa; int gk;
        if (k0 < H_) { pa = g.Aa; gk = k0; }
        else         { pa = g.Ab; gk = k0 - H_; }
        size_t ga = (size_t)(bm * 128 + r0) * H_ + gk + cg8;
        cp16(sb + so,              pa + ga);
        cp16(sb + so2,             pa + ga + 64 * H_);
        size_t gw = (size_t)(bn * 128 + r0) * g.K + k0 + cg8;
        cp16(sb + MSZ2 + so,       g.W_hi + gw);
        cp16(sb + MSZ2 + so2,      g.W_hi + gw + (size_t)64 * g.K);
        cp16(sb + 2 * MSZ2 + so,   g.W_lo + gw);
        cp16(sb + 2 * MSZ2 + so2,  g.W_lo + gw + (size_t)64 * g.K);
    };

    auto compute_chunk = [&](int stage) {
        uint32_t sb = sb0 + stage * STG2;
#pragma unroll
        for (int k16 = 0; k16 < 4; k16++) {
            uint32_t bh[8], bl[8];
#pragma unroll
            for (int nt2 = 0; nt2 < 2; nt2++) {
                int row = wn * 32 + nt2 * 16 + ((lane >> 4) & 1) * 8 + (lane & 7);
                int colh = k16 * 16 + ((lane >> 3) & 1) * 8;
                uint32_t off = (uint32_t)(row * ASTR2 + colh) * 2;
                ldm_x4(bh + nt2 * 4, sb + MSZ2 + off);
                ldm_x4(bl + nt2 * 4, sb + 2 * MSZ2 + off);
            }
#pragma unroll
            for (int mt = 0; mt < 2; mt++) {
                int row = wm * 32 + mt * 16 + (lane & 7) + ((lane >> 3) & 1) * 8;
                int colh = k16 * 16 + ((lane >> 4) & 1) * 8;
                uint32_t off = (uint32_t)(row * ASTR2 + colh) * 2;
                uint32_t a[4];
                ldm_x4(a, sb + off);
#pragma unroll
                for (int nt = 0; nt < 4; nt++) {
                    mma16816(acc[mt][nt], a, bh + nt * 2);
                    mma16816(acc[mt][nt], a, bl + nt * 2);
                }
            }
        }
    };

    load_chunk(0, 0); cp_commit();
    if (n > 1) load_chunk(1, 1);
    cp_commit();
    for (int i = 0; i < n; i++) {
        cp_wait1();
        __syncthreads();
        // safe with 3 stages: (i+2)%3 == (i-1)%3, whose compute finished
        // before every thread's arrival at the barrier above
        if (i + 2 < n) load_chunk(i + 2, (i + 2) % 3);
        cp_commit();
        compute_chunk(i % 3);
    }
    cp_wait0();
    __syncthreads();
}

// ================== persistent recurrence kernel ============================
__device__ __forceinline__ void grid_barrier() {
    __syncthreads();
    if (threadIdx.x == 0) {
        __threadfence();
        int gen = g_bar_gen;
        if (atomicAdd(&g_bar_count, 1) == NCTA_STEP - 1) {
            g_bar_count = 0;
            __threadfence();
            g_bar_gen = gen + 1;
        } else {
            while (g_bar_gen == gen) { }
        }
        __threadfence();
    }
    __syncthreads();
}

// roles: 0 = L0(s) gates (K=256); 1 = L1(s-1) gates (K=512 concat)
__global__ void __launch_bounds__(512, 1)
k_rnn() {
    extern __shared__ __align__(16) char smbuf[];
    int tid = threadIdx.x, lane = tid & 31, wid = tid >> 5;
    int wm = wid >> 2, wn = wid & 3;
    int role = blockIdx.x >> 6;          // 64 CTAs per role
    int tile = blockIdx.x & 63;
    int bn = tile & 7, bm = tile >> 3;   // 8 x 8 tiles of 128x128
    float* Cst = (float*)smbuf;

    for (int s = 0; s <= T_; s++) {
        int t = role ? (s - 1) : s;
        bool active = role ? (s >= 1) : (s < T_);
        if (active) {
            int r = t & 1, w = 1 - r;
            Core512Args g;
            const float *addend, *bias, *c_prev;
            float *c_new;
            h16 *o_h, *hr = nullptr;
            if (role == 0) {
                g = {g_h0 + r * BH_, g_h0 + r * BH_, g_Whh0_hi, g_Whh0_lo, H_};
                addend = g_A0 + (size_t)t * B_ * G_;  bias = nullptr;
                c_prev = g_c0 + r * BH_; c_new = g_c0 + w * BH_;
                o_h = g_h0 + w * BH_;
            } else {
                g = {g_h0 + w * BH_, g_h1 + r * BH_,   // h0(t) in slot 1-(t&1)
                     g_W1_hi, g_W1_lo, 2 * H_};
                addend = nullptr;  bias = g_b1r;
                c_prev = g_c1 + r * BH_; c_new = g_c1 + w * BH_;
                o_h = g_h1 + w * BH_;
                hr = g_hsr + (size_t)t * BH_;
            }

            float acc[2][4][4] = {};
            gemm_core512(g, smbuf, bm, bn, acc);

            // stage C
#pragma unroll
            for (int mt = 0; mt < 2; mt++)
#pragma unroll
                for (int nt = 0; nt < 4; nt++) {
                    int r0 = wm * 32 + mt * 16 + (lane >> 2);
                    int c0 = wn * 32 + nt * 8 + (lane & 3) * 2;
                    Cst[r0 * CST_STR + c0]           = acc[mt][nt][0];
                    Cst[r0 * CST_STR + c0 + 1]       = acc[mt][nt][1];
                    Cst[(r0 + 8) * CST_STR + c0]     = acc[mt][nt][2];
                    Cst[(r0 + 8) * CST_STR + c0 + 1] = acc[mt][nt][3];
                }
            __syncthreads();

            // LSTM cell epilogue: 512 threads, each 8 units of one row
            int grow0 = bm * 128, gcol0 = bn * 128;
            int row = tid >> 2, q = tid & 3;
#pragma unroll
            for (int u8 = 0; u8 < 8; u8++) {
                int ul = q * 8 + u8;
                float gg[4];
                const float* cp = Cst + row * CST_STR + ul * 4;
                if (role == 0) {
                    float4 ad = *(const float4*)(addend + (size_t)(grow0 + row) * G_ + gcol0 + ul * 4);
                    gg[0] = cp[0] + ad.x; gg[1] = cp[1] + ad.y;
                    gg[2] = cp[2] + ad.z; gg[3] = cp[3] + ad.w;
                } else {
                    const float* br = bias + gcol0 + ul * 4;
                    gg[0] = cp[0] + br[0]; gg[1] = cp[1] + br[1];
                    gg[2] = cp[2] + br[2]; gg[3] = cp[3] + br[3];
                }
                size_t ci = (size_t)(grow0 + row) * H_ + (gcol0 >> 2) + ul;
                float c = fmaf(sigm(gg[1]), c_prev[ci], sigm(gg[0]) * tanhf(gg[2]));
                c_new[ci] = c;
                float h = sigm(gg[3]) * tanhf(c);
                o_h[ci] = __float2half_rn(h);
                if (hr) hr[ci] = __float2half_rn(fmaxf(h, 0.f));
            }
        }
        if (s < T_) grid_barrier();
    }
}

// ======================= prep: split + gate reorder =========================
__global__ void k_prep(const float* __restrict__ Wi2, const float* __restrict__ Wi3,
                       const float* __restrict__ Wo1, const float* __restrict__ Wo2,
                       const float* __restrict__ Wih0, const float* __restrict__ Whh0,
                       const float* __restrict__ bih0, const float* __restrict__ bhh0,
                       const float* __restrict__ Wih1, const float* __restrict__ Whh1,
                       const float* __restrict__ bih1, const float* __restrict__ bhh1) {
    int idx = blockIdx.x * blockDim.x + threadIdx.x;
    int stride = gridDim.x * blockDim.x;
    for (int i = idx; i < H_ * H_; i += stride) {
        wsplit(g_Wi2_hi, g_Wi2_lo, i, Wi2[i]);
        wsplit(g_Wi3_hi, g_Wi3_lo, i, Wi3[i]);
        wsplit(g_Wo1_hi, g_Wo1_lo, i, Wo1[i]);
        wsplit(g_Wo2_hi, g_Wo2_lo, i, Wo2[i]);
    }
    for (int i = idx; i < G_ * H_; i += stride) {
        int rr = i / H_, k = i - rr * H_;
        int j = rr >> 2, gg = rr & 3;
        int src = (gg * H_ + j) * H_ + k;
        wsplit(g_Wih0_hi, g_Wih0_lo, i, Wih0[src]);
        wsplit(g_Whh0_hi, g_Whh0_lo, i, Whh0[src]);
    }
    for (int i = idx; i < G_ * 2 * H_; i += stride) {
        int rr = i / (2 * H_), k = i - rr * (2 * H_);
        int j = rr >> 2, gg = rr & 3;
        float v = (k < H_) ? Wih1[(gg * H_ + j) * H_ + k]
                           : Whh1[(gg * H_ + j) * H_ + (k - H_)];
        wsplit(g_W1_hi, g_W1_lo, i, v);
    }
    if (idx < G_) {
        int j = idx >> 2, gg = idx & 3;
        g_b0r[idx] = bih0[gg * H_ + j] + bhh0[gg * H_ + j];
        g_b1r[idx] = bih1[gg * H_ + j] + bhh1[gg * H_ + j];
    }
    if (idx == 0) g_bar_count = 0;
}

__global__ void k_zero() {
    int idx = blockIdx.x * blockDim.x + threadIdx.x;
    int stride = gridDim.x * blockDim.x;
    for (int i = idx; i < 2 * BH_; i += stride) {
        g_h0[i] = __float2half_rn(0.f);
        g_h1[i] = __float2half_rn(0.f);
        g_c0[i] = 0.f; g_c1[i] = 0.f;
    }
}

// ===================== input MLP stage 1 (K=6) ==============================
__global__ void __launch_bounds__(256)
k_in1(const float* __restrict__ x, const float* __restrict__ Wi1,
      const float* __restrict__ bi1) {
    __shared__ float Ws[H_ * LAG_];
    __shared__ float bs[H_];
    int tid = threadIdx.x;
    for (int i = tid; i < H_ * LAG_; i += 256) Ws[i] = Wi1[i];
    if (tid < H_) bs[tid] = bi1[tid];
    __syncthreads();
    int j = tid;
    for (int rr = 0; rr < 64; rr++) {
        int row = blockIdx.x * 64 + rr;
        const float* xr = x + (size_t)row * LAG_;
        float acc = bs[j];
#pragma unroll
        for (int k = 0; k < LAG_; k++) acc = fmaf(xr[k], Ws[j * LAG_ + k], acc);
        g_u[(size_t)row * H_ + j] = __float2half_rn(fmaxf(acc, 0.f));
    }
}

// ===================== output head (N=6) ====================================
__global__ void __launch_bounds__(256)
k_out3(const float* __restrict__ Ain, const float* __restrict__ Wo3,
       const float* __restrict__ bo3, float* __restrict__ y) {
    __shared__ float Ws[LAG_ * H_];
    int tid = threadIdx.x;
    for (int i = tid; i < LAG_ * H_; i += 256) Ws[i] = Wo3[i];
    __syncthreads();
    int wrp = tid >> 5, lane = tid & 31;
    int row = blockIdx.x * 8 + wrp;
    const float* ar = Ain + (size_t)row * H_;
    float acc[LAG_] = {};
    for (int k = lane; k < H_; k += 32) {
        float a = ar[k];
#pragma unroll
        for (int o = 0; o < LAG_; o++) acc[o] = fmaf(a, Ws[o * H_ + k], acc[o]);
    }
#pragma unroll
    for (int o = 0; o < LAG_; o++) {
        float v = acc[o];
#pragma unroll
        for (int off = 16; off; off >>= 1) v += __shfl_xor_sync(0xffffffffu, v, off);
        if (lane == 0) y[(size_t)row * LAG_ + o] = v + bo3[o];
    }
}

// ============================== host ========================================
extern "C" void kernel_launch(void* const* d_in, const int* in_sizes, int n_in,
                              void* d_out, int out_size) {
    const float* x    = (const float*)d_in[0];
    const float* Wi1  = (const float*)d_in[1];  const float* bi1 = (const float*)d_in[2];
    const float* Wi2  = (const float*)d_in[3];  const float* bi2 = (const float*)d_in[4];
    const float* Wi3  = (const float*)d_in[5];  const float* bi3 = (const float*)d_in[6];
    const float* Wih0 = (const float*)d_in[7];  const float* Whh0 = (const float*)d_in[8];
    const float* bih0 = (const float*)d_in[9];  const float* bhh0 = (const float*)d_in[10];
    const float* Wih1 = (const float*)d_in[11]; const float* Whh1 = (const float*)d_in[12];
    const float* bih1 = (const float*)d_in[13]; const float* bhh1 = (const float*)d_in[14];
    const float* Wo1  = (const float*)d_in[15]; const float* bo1 = (const float*)d_in[16];
    const float* Wo2  = (const float*)d_in[17]; const float* bo2 = (const float*)d_in[18];
    const float* Wo3  = (const float*)d_in[19]; const float* bo3 = (const float*)d_in[20];
    float* y = (float*)d_out;

    cudaFuncSetAttribute(wm_gemm<0>, cudaFuncAttributeMaxDynamicSharedMemorySize, SMEM_SZ);
    cudaFuncSetAttribute(wm_gemm<3>, cudaFuncAttributeMaxDynamicSharedMemorySize, SMEM_SZ);
    cudaFuncSetAttribute(wm_gemm<4>, cudaFuncAttributeMaxDynamicSharedMemorySize, SMEM_SZ);
    cudaFuncSetAttribute(k_rnn,      cudaFuncAttributeMaxDynamicSharedMemorySize, RSMEM);

    float *A0, *bufB, *b0r;
    h16 *u, *v, *hsr;
    h16 *Wi2h, *Wi2l, *Wi3h, *Wi3l, *Wo1h, *Wo1l, *Wo2h, *Wo2l, *Wih0h, *Wih0l;
    cudaGetSymbolAddress((void**)&A0,   g_A0);
    cudaGetSymbolAddress((void**)&bufB, g_bufB);
    cudaGetSymbolAddress((void**)&b0r,  g_b0r);
    cudaGetSymbolAddress((void**)&u,    g_u);
    cudaGetSymbolAddress((void**)&v,    g_v);
    cudaGetSymbolAddress((void**)&hsr,  g_hsr);
    cudaGetSymbolAddress((void**)&Wi2h, g_Wi2_hi); cudaGetSymbolAddress((void**)&Wi2l, g_Wi2_lo);
    cudaGetSymbolAddress((void**)&Wi3h, g_Wi3_hi); cudaGetSymbolAddress((void**)&Wi3l, g_Wi3_lo);
    cudaGetSymbolAddress((void**)&Wo1h, g_Wo1_hi); cudaGetSymbolAddress((void**)&Wo1l, g_Wo1_lo);
    cudaGetSymbolAddress((void**)&Wo2h, g_Wo2_hi); cudaGetSymbolAddress((void**)&Wo2l, g_Wo2_lo);
    cudaGetSymbolAddress((void**)&Wih0h, g_Wih0_hi); cudaGetSymbolAddress((void**)&Wih0l, g_Wih0_lo);

    k_prep<<<512, 512>>>(Wi2, Wi3, Wo1, Wo2, Wih0, Whh0, bih0, bhh0,
                         Wih1, Whh1, bih1, bhh1);
    k_zero<<<512, 512>>>();

    // input MLP
    k_in1<<<NR_ / 64, 256>>>(x, Wi1, bi1);
    dim3 blk(256);
    dim3 gMLP(H_ / 128, NR_ / 128);              // (2, 1024)
    wm_gemm<3><<<gMLP, blk, SMEM_SZ>>>(u, Wi2h, Wi2l, bi2, v, nullptr, H_);
    wm_gemm<3><<<gMLP, blk, SMEM_SZ>>>(v, Wi3h, Wi3l, bi3, u, nullptr, H_);

    // hoisted layer-0 input projection: A0 = u @ Wih0r^T + b0r
    dim3 gA0(G_ / 128, NR_ / 128);               // (8, 1024)
    wm_gemm<0><<<gA0, blk, SMEM_SZ>>>(u, Wih0h, Wih0l, b0r, nullptr, A0, G_);

    // persistent 2-role recurrence: 128 CTAs x 512 threads, all SM-resident
    k_rnn<<<NCTA_STEP, 512, RSMEM>>>();

    // output MLP
    wm_gemm<3><<<gMLP, blk, SMEM_SZ>>>(hsr, Wo1h, Wo1l, bo1, v, nullptr, H_);
    wm_gemm<4><<<gMLP, blk, SMEM_SZ>>>(v, Wo2h, Wo2l, bo2, nullptr, bufB, H_);
    k_out3<<<NR_ / 8, 256>>>(bufB, Wo3, bo3, y);
}

// round 12
// speedup vs baseline: 1.6020x; 1.1372x over previous
#include <cuda_runtime.h>
#include <cuda_fp16.h>
#include <math.h>
#include <stdint.h>

#define T_    128
#define B_    1024
#define LAG_  6
#define H_    256
#define G_    1024            // 4*H
#define NR_   (T_*B_)         // 131072
#define BH_   (B_*H_)         // 262144

typedef __half h16;

// ============================ device scratch ================================
__device__ float g_A0[(size_t)NR_*G_];          // input-gate precompute (L0)
__device__ float g_bufB[NR_*H_];                // f32 staging before out3
__device__ h16 g_u[NR_*H_];
__device__ h16 g_v[NR_*H_];
__device__ h16 g_hsr[NR_*H_];                   // relu(h1) per t
__device__ h16 g_h0[2*BH_];
__device__ h16 g_h1[2*BH_];
__device__ float g_c0[2*BH_], g_c1[2*BH_];
// split fp16 weights (row-major [N][K])
__device__ h16 g_Wi2_hi[H_*H_], g_Wi2_lo[H_*H_];
__device__ h16 g_Wi3_hi[H_*H_], g_Wi3_lo[H_*H_];
__device__ h16 g_Wo1_hi[H_*H_], g_Wo1_lo[H_*H_];
__device__ h16 g_Wo2_hi[H_*H_], g_Wo2_lo[H_*H_];
__device__ h16 g_Wih0_hi[G_*H_], g_Wih0_lo[G_*H_];   // gate-interleaved rows
__device__ h16 g_Whh0_hi[G_*H_], g_Whh0_lo[G_*H_];
__device__ h16 g_W1_hi[G_*2*H_], g_W1_lo[G_*2*H_];   // [1024][512] = [Wih1|Whh1]
__device__ float g_b0r[G_], g_b1r[G_];
// grid barrier state
__device__ int g_bar_count;
__device__ volatile int g_bar_gen;

// ======================= low-level helpers ==================================
__device__ __forceinline__ void wsplit(h16* hi, h16* lo, size_t i, float v) {
    h16 h = __float2half_rn(v);
    hi[i] = h;
    lo[i] = __float2half_rn(v - __half2float(h));
}
__device__ __forceinline__ float sigm(float x) { return 1.f / (1.f + expf(-x)); }
__device__ __forceinline__ uint32_t smem_u32(const void* p) {
    uint32_t a;
    asm("{ .reg .u64 t; cvta.to.shared.u64 t, %1; cvt.u32.u64 %0, t; }" : "=r"(a) : "l"(p));
    return a;
}
__device__ __forceinline__ void cp16(uint32_t dst, const void* src) {
    asm volatile("cp.async.cg.shared.global [%0], [%1], 16;" :: "r"(dst), "l"(src));
}
__device__ __forceinline__ void cp_commit() { asm volatile("cp.async.commit_group;" ::: "memory"); }
__device__ __forceinline__ void cp_wait1()  { asm volatile("cp.async.wait_group 1;" ::: "memory"); }
__device__ __forceinline__ void cp_wait0()  { asm volatile("cp.async.wait_group 0;" ::: "memory"); }
__device__ __forceinline__ void ldm_x4(uint32_t* r, uint32_t addr) {
    asm volatile("ldmatrix.sync.aligned.m8n8.x4.shared.b16 {%0,%1,%2,%3}, [%4];"
                 : "=r"(r[0]), "=r"(r[1]), "=r"(r[2]), "=r"(r[3]) : "r"(addr));
}
__device__ __forceinline__ void mma16816(float* c, const uint32_t* a, const uint32_t* b) {
    asm volatile("mma.sync.aligned.m16n8k16.row.col.f32.f16.f16.f32 "
                 "{%0,%1,%2,%3}, {%4,%5,%6,%7}, {%8,%9}, {%0,%1,%2,%3};"
                 : "+f"(c[0]), "+f"(c[1]), "+f"(c[2]), "+f"(c[3])
                 : "r"(a[0]), "r"(a[1]), "r"(a[2]), "r"(a[3]), "r"(b[0]), "r"(b[1]));
}

#define CST_STR 132
// MLP core (256 thr): stage = A[128][40] + Wh[128][40] + Wl[128][40]
#define ASTR  40
#define MSZ1  10240
#define STG1  (3 * MSZ1)           // 30720 per stage, 2 stages
#define SMEM_SZ 67584              // >= 2*STG1 (61440) and C staging (67584)
// recurrence core (512 thr): BM=64, BN=128, BK=64
#define ASTR3 72
#define A3SZ  (64 * ASTR3 * 2)     // 9216
#define W3SZ  (128 * ASTR3 * 2)    // 18432
#define STG3  (A3SZ + 2 * W3SZ)    // 46080 per stage (A, Wh, Wl)
#define RSMEM (3 * STG3)           // 138240, 3 stages, 1 CTA/SM
#define NCTA_STEP 128

// ============ MLP core (256 threads, BM=128, BN=128, K=256, 2-stage) ========
struct CoreArgs {
    const h16 *A, *W_hi, *W_lo;
};

__device__ __forceinline__ void gemm_core256(const CoreArgs& g, char* smbuf,
                                             int bm, int bn, float acc[4][4][4]) {
    int tid = threadIdx.x, lane = tid & 31, wid = tid >> 5;
    uint32_t sb0 = smem_u32(smbuf);
    int r0 = tid >> 2, cg8 = (tid & 3) << 3;
    uint32_t so  = (uint32_t)(r0 * ASTR + cg8) * 2;
    uint32_t so2 = so + 64 * ASTR * 2;
    int wm = wid >> 2, wn = wid & 3;

    auto load_chunk = [&](int c, int stage) {
        uint32_t sb = sb0 + stage * STG1;
        int k0 = c << 5;
        size_t ga = (size_t)(bm * 128 + r0) * H_ + k0 + cg8;
        cp16(sb + so,              g.A + ga);
        cp16(sb + so2,             g.A + ga + 64 * H_);
        size_t gw = (size_t)(bn * 128 + r0) * H_ + k0 + cg8;
        cp16(sb + MSZ1 + so,       g.W_hi + gw);
        cp16(sb + MSZ1 + so2,      g.W_hi + gw + 64 * H_);
        cp16(sb + 2 * MSZ1 + so,   g.W_lo + gw);
        cp16(sb + 2 * MSZ1 + so2,  g.W_lo + gw + 64 * H_);
    };

    auto compute_chunk = [&](int stage) {
        uint32_t sb = sb0 + stage * STG1;
#pragma unroll
        for (int k16 = 0; k16 < 2; k16++) {
            uint32_t bh[8], bl[8];
#pragma unroll
            for (int nt2 = 0; nt2 < 2; nt2++) {
                int row = wn * 32 + nt2 * 16 + ((lane >> 4) & 1) * 8 + (lane & 7);
                int colh = k16 * 16 + ((lane >> 3) & 1) * 8;
                uint32_t off = (uint32_t)(row * ASTR + colh) * 2;
                ldm_x4(bh + nt2 * 4, sb + MSZ1 + off);
                ldm_x4(bl + nt2 * 4, sb + 2 * MSZ1 + off);
            }
#pragma unroll
            for (int mt = 0; mt < 4; mt++) {
                int row = wm * 64 + mt * 16 + (lane & 7) + ((lane >> 3) & 1) * 8;
                int colh = k16 * 16 + ((lane >> 4) & 1) * 8;
                uint32_t off = (uint32_t)(row * ASTR + colh) * 2;
                uint32_t a[4];
                ldm_x4(a, sb + off);
#pragma unroll
                for (int nt = 0; nt < 4; nt++) {
                    mma16816(acc[mt][nt], a, bh + nt * 2);
                    mma16816(acc[mt][nt], a, bl + nt * 2);
                }
            }
        }
    };

    load_chunk(0, 0); cp_commit();
    load_chunk(1, 1); cp_commit();
    for (int i = 0; i < 8; i++) {
        cp_wait1();
        __syncthreads();
        compute_chunk(i & 1);
        __syncthreads();
        if (i + 2 < 8) load_chunk(i + 2, i & 1);
        cp_commit();
    }
    cp_wait0();
    __syncthreads();
}

// ================= generic pipelined GEMM kernel (MLP / A0) =================
// MODE 0: out_f32 = D + bias ; MODE 3: relu fp16 ; MODE 4: relu f32
template<int MODE>
__global__ void __launch_bounds__(256, 2)
wm_gemm(const h16* __restrict__ A, const h16* __restrict__ W_hi,
        const h16* __restrict__ W_lo, const float* __restrict__ bias,
        h16* __restrict__ o_h, float* __restrict__ out_f32, int ldc) {
    extern __shared__ __align__(16) char smbuf[];
    int tid = threadIdx.x, lane = tid & 31, wid = tid >> 5;
    int wm = wid >> 2, wn = wid & 3;
    int bn = blockIdx.x, bm = blockIdx.y;

    float acc[4][4][4] = {};
    CoreArgs g{A, W_hi, W_lo};
    gemm_core256(g, smbuf, bm, bn, acc);

    float* Cst = (float*)smbuf;
#pragma unroll
    for (int mt = 0; mt < 4; mt++)
#pragma unroll
        for (int nt = 0; nt < 4; nt++) {
            int r0 = wm * 64 + mt * 16 + (lane >> 2);
            int c0 = wn * 32 + nt * 8 + (lane & 3) * 2;
            Cst[r0 * CST_STR + c0]           = acc[mt][nt][0];
            Cst[r0 * CST_STR + c0 + 1]       = acc[mt][nt][1];
            Cst[(r0 + 8) * CST_STR + c0]     = acc[mt][nt][2];
            Cst[(r0 + 8) * CST_STR + c0 + 1] = acc[mt][nt][3];
        }
    __syncthreads();

    int grow0 = bm * 128, gcol0 = bn * 128;
    int row = tid >> 1, half = tid & 1;
    const float* crow = Cst + row * CST_STR + half * 64;
    const float* brow = bias + gcol0 + half * 64;

    if (MODE == 0 || MODE == 4) {
        float* orow = out_f32 + (size_t)(grow0 + row) * ldc + gcol0 + half * 64;
#pragma unroll
        for (int j = 0; j < 64; j += 4) {
            float4 v;
            v.x = crow[j + 0] + brow[j + 0];
            v.y = crow[j + 1] + brow[j + 1];
            v.z = crow[j + 2] + brow[j + 2];
            v.w = crow[j + 3] + brow[j + 3];
            if (MODE == 4) {
                v.x = fmaxf(v.x, 0.f); v.y = fmaxf(v.y, 0.f);
                v.z = fmaxf(v.z, 0.f); v.w = fmaxf(v.w, 0.f);
            }
            *(float4*)(orow + j) = v;
        }
    } else {  // MODE 3: relu -> fp16
        size_t obase = (size_t)(grow0 + row) * ldc + gcol0 + half * 64;
#pragma unroll
        for (int j0 = 0; j0 < 64; j0 += 8) {
            h16 vh[8];
#pragma unroll
            for (int j = 0; j < 8; j++)
                vh[j] = __float2half_rn(fmaxf(crow[j0 + j] + brow[j0 + j], 0.f));
            *(uint4*)(o_h + obase + j0) = *(uint4*)vh;
        }
    }
}

// ====== recurrence core (512 thr, BM=64, BN=128, BK=64, 3-stage ring) =======
// warp grid 2x8: warp tile 32(M) x 16(N)
__device__ __forceinline__ void gemm_core64(const h16* Aa, const h16* Ab,
                                            const h16* W_hi, const h16* W_lo, int K,
                                            char* smbuf, int bm, int bn,
                                            float acc[2][2][4]) {
    int tid = threadIdx.x, lane = tid & 31, wid = tid >> 5;
    int wm = wid >> 3, wn = wid & 7;
    uint32_t sb0 = smem_u32(smbuf);
    int n = K >> 6;
    int r0 = tid >> 3, cg8 = (tid & 7) << 3;
    uint32_t so  = (uint32_t)(r0 * ASTR3 + cg8) * 2;
    uint32_t so2 = so + 64 * ASTR3 * 2;

    auto load_chunk = [&](int c, int stage) {
        uint32_t sb = sb0 + stage * STG3;
        int k0 = c << 6;
        const h16* pa; int gk;
        if (k0 < H_) { pa = Aa; gk = k0; }
        else         { pa = Ab; gk = k0 - H_; }
        // A: 64 rows
        size_t ga = (size_t)(bm * 64 + r0) * H_ + gk + cg8;
        cp16(sb + so, pa + ga);
        // W: 128 rows (two passes)
        size_t gw = (size_t)(bn * 128 + r0) * K + k0 + cg8;
        cp16(sb + A3SZ + so,          W_hi + gw);
        cp16(sb + A3SZ + so2,         W_hi + gw + (size_t)64 * K);
        cp16(sb + A3SZ + W3SZ + so,   W_lo + gw);
        cp16(sb + A3SZ + W3SZ + so2,  W_lo + gw + (size_t)64 * K);
    };

    auto compute_chunk = [&](int stage) {
        uint32_t sb = sb0 + stage * STG3;
#pragma unroll
        for (int k16 = 0; k16 < 4; k16++) {
            uint32_t bh[4], bl[4];
            {
                int row = wn * 16 + ((lane >> 4) & 1) * 8 + (lane & 7);
                int colh = k16 * 16 + ((lane >> 3) & 1) * 8;
                uint32_t off = (uint32_t)(row * ASTR3 + colh) * 2;
                ldm_x4(bh, sb + A3SZ + off);
                ldm_x4(bl, sb + A3SZ + W3SZ + off);
            }
#pragma unroll
            for (int mt = 0; mt < 2; mt++) {
                int row = wm * 32 + mt * 16 + (lane & 7) + ((lane >> 3) & 1) * 8;
                int colh = k16 * 16 + ((lane >> 4) & 1) * 8;
                uint32_t off = (uint32_t)(row * ASTR3 + colh) * 2;
                uint32_t a[4];
                ldm_x4(a, sb + off);
#pragma unroll
                for (int nt = 0; nt < 2; nt++) {
                    mma16816(acc[mt][nt], a, bh + nt * 2);
                    mma16816(acc[mt][nt], a, bl + nt * 2);
                }
            }
        }
    };

    load_chunk(0, 0); cp_commit();
    if (n > 1) load_chunk(1, 1);
    cp_commit();
    for (int i = 0; i < n; i++) {
        cp_wait1();
        __syncthreads();
        if (i + 2 < n) load_chunk(i + 2, (i + 2) % 3);
        cp_commit();
        compute_chunk(i % 3);
    }
    cp_wait0();
    __syncthreads();
}

// stage C (64 x 128) + LSTM cell epilogue for one BM=64 tile
__device__ __forceinline__ void lstm_tail64(float* Cst, const float acc[2][2][4],
                                            int bm, int bn,
                                            const float* addend, const float* bias,
                                            const float* c_prev, float* c_new,
                                            h16* o_h, h16* hr) {
    int tid = threadIdx.x, lane = tid & 31, wid = tid >> 5;
    int wm = wid >> 3, wn = wid & 7;
#pragma unroll
    for (int mt = 0; mt < 2; mt++)
#pragma unroll
        for (int nt = 0; nt < 2; nt++) {
            int r0 = wm * 32 + mt * 16 + (lane >> 2);
            int c0 = wn * 16 + nt * 8 + (lane & 3) * 2;
            Cst[r0 * CST_STR + c0]           = acc[mt][nt][0];
            Cst[r0 * CST_STR + c0 + 1]       = acc[mt][nt][1];
            Cst[(r0 + 8) * CST_STR + c0]     = acc[mt][nt][2];
            Cst[(r0 + 8) * CST_STR + c0 + 1] = acc[mt][nt][3];
        }
    __syncthreads();

    int grow0 = bm * 64, gcol0 = bn * 128;
    int row = tid >> 3, q = tid & 7;
#pragma unroll
    for (int uu = 0; uu < 4; uu++) {
        int ul = q * 4 + uu;
        float gg[4];
        const float* cp = Cst + row * CST_STR + ul * 4;
        if (addend) {
            float4 ad = *(const float4*)(addend + (size_t)(grow0 + row) * G_ + gcol0 + ul * 4);
            gg[0] = cp[0] + ad.x; gg[1] = cp[1] + ad.y;
            gg[2] = cp[2] + ad.z; gg[3] = cp[3] + ad.w;
        } else {
            const float* br = bias + gcol0 + ul * 4;
            gg[0] = cp[0] + br[0]; gg[1] = cp[1] + br[1];
            gg[2] = cp[2] + br[2]; gg[3] = cp[3] + br[3];
        }
        size_t ci = (size_t)(grow0 + row) * H_ + (gcol0 >> 2) + ul;
        float c = fmaf(sigm(gg[1]), c_prev[ci], sigm(gg[0]) * tanhf(gg[2]));
        c_new[ci] = c;
        float h = sigm(gg[3]) * tanhf(c);
        o_h[ci] = __float2half_rn(h);
        if (hr) hr[ci] = __float2half_rn(fmaxf(h, 0.f));
    }
    __syncthreads();
}

// ================== persistent recurrence kernel ============================
__device__ __forceinline__ void grid_barrier() {
    __syncthreads();
    if (threadIdx.x == 0) {
        __threadfence();
        int gen = g_bar_gen;
        if (atomicAdd(&g_bar_count, 1) == NCTA_STEP - 1) {
            g_bar_count = 0;
            __threadfence();
            g_bar_gen = gen + 1;
        } else {
            while (g_bar_gen == gen) { }
        }
        __threadfence();
    }
    __syncthreads();
}

// each CTA owns one 64x128 tile; per step it does L0(s) then L1(s-1) on it
__global__ void __launch_bounds__(512, 1)
k_rnn() {
    extern __shared__ __align__(16) char smbuf[];
    int bi = blockIdx.x;
    int bm = bi >> 3, bn = bi & 7;       // 16 x 8 tiles of 64x128
    float* Cst = (float*)smbuf;

    for (int s = 0; s <= T_; s++) {
        // ---- role 0: layer-0 gates for t = s ----
        if (s < T_) {
            int t = s, r = t & 1, w = 1 - r;
            float acc[2][2][4] = {};
            gemm_core64(g_h0 + r * BH_, g_h0 + r * BH_, g_Whh0_hi, g_Whh0_lo, H_,
                        smbuf, bm, bn, acc);
            lstm_tail64(Cst, acc, bm, bn,
                        g_A0 + (size_t)t * B_ * G_, nullptr,
                        g_c0 + r * BH_, g_c0 + w * BH_,
                        g_h0 + w * BH_, nullptr);
        }
        // ---- role 1: layer-1 gates for t = s - 1 ----
        if (s >= 1) {
            int t = s - 1, r = t & 1, w = 1 - r;
            float acc[2][2][4] = {};
            // h0(t) lives in slot 1-(t&1) = w
            gemm_core64(g_h0 + w * BH_, g_h1 + r * BH_, g_W1_hi, g_W1_lo, 2 * H_,
                        smbuf, bm, bn, acc);
            lstm_tail64(Cst, acc, bm, bn,
                        nullptr, g_b1r,
                        g_c1 + r * BH_, g_c1 + w * BH_,
                        g_h1 + w * BH_, g_hsr + (size_t)t * BH_);
        }
        if (s < T_) grid_barrier();
    }
}

// ======================= prep: split + gate reorder =========================
__global__ void k_prep(const float* __restrict__ Wi2, const float* __restrict__ Wi3,
                       const float* __restrict__ Wo1, const float* __restrict__ Wo2,
                       const float* __restrict__ Wih0, const float* __restrict__ Whh0,
                       const float* __restrict__ bih0, const float* __restrict__ bhh0,
                       const float* __restrict__ Wih1, const float* __restrict__ Whh1,
                       const float* __restrict__ bih1, const float* __restrict__ bhh1) {
    int idx = blockIdx.x * blockDim.x + threadIdx.x;
    int stride = gridDim.x * blockDim.x;
    for (int i = idx; i < H_ * H_; i += stride) {
        wsplit(g_Wi2_hi, g_Wi2_lo, i, Wi2[i]);
        wsplit(g_Wi3_hi, g_Wi3_lo, i, Wi3[i]);
        wsplit(g_Wo1_hi, g_Wo1_lo, i, Wo1[i]);
        wsplit(g_Wo2_hi, g_Wo2_lo, i, Wo2[i]);
    }
    for (int i = idx; i < G_ * H_; i += stride) {
        int rr = i / H_, k = i - rr * H_;
        int j = rr >> 2, gg = rr & 3;
        int src = (gg * H_ + j) * H_ + k;
        wsplit(g_Wih0_hi, g_Wih0_lo, i, Wih0[src]);
        wsplit(g_Whh0_hi, g_Whh0_lo, i, Whh0[src]);
    }
    for (int i = idx; i < G_ * 2 * H_; i += stride) {
        int rr = i / (2 * H_), k = i - rr * (2 * H_);
        int j = rr >> 2, gg = rr & 3;
        float v = (k < H_) ? Wih1[(gg * H_ + j) * H_ + k]
                           : Whh1[(gg * H_ + j) * H_ + (k - H_)];
        wsplit(g_W1_hi, g_W1_lo, i, v);
    }
    if (idx < G_) {
        int j = idx >> 2, gg = idx & 3;
        g_b0r[idx] = bih0[gg * H_ + j] + bhh0[gg * H_ + j];
        g_b1r[idx] = bih1[gg * H_ + j] + bhh1[gg * H_ + j];
    }
    if (idx == 0) g_bar_count = 0;
}

__global__ void k_zero() {
    int idx = blockIdx.x * blockDim.x + threadIdx.x;
    int stride = gridDim.x * blockDim.x;
    for (int i = idx; i < 2 * BH_; i += stride) {
        g_h0[i] = __float2half_rn(0.f);
        g_h1[i] = __float2half_rn(0.f);
        g_c0[i] = 0.f; g_c1[i] = 0.f;
    }
}

// ===================== input MLP stage 1 (K=6) ==============================
__global__ void __launch_bounds__(256)
k_in1(const float* __restrict__ x, const float* __restrict__ Wi1,
      const float* __restrict__ bi1) {
    __shared__ float Ws[H_ * LAG_];
    __shared__ float bs[H_];
    int tid = threadIdx.x;
    for (int i = tid; i < H_ * LAG_; i += 256) Ws[i] = Wi1[i];
    if (tid < H_) bs[tid] = bi1[tid];
    __syncthreads();
    int j = tid;
    for (int rr = 0; rr < 64; rr++) {
        int row = blockIdx.x * 64 + rr;
        const float* xr = x + (size_t)row * LAG_;
        float acc = bs[j];
#pragma unroll
        for (int k = 0; k < LAG_; k++) acc = fmaf(xr[k], Ws[j * LAG_ + k], acc);
        g_u[(size_t)row * H_ + j] = __float2half_rn(fmaxf(acc, 0.f));
    }
}

// ===================== output head (N=6) ====================================
__global__ void __launch_bounds__(256)
k_out3(const float* __restrict__ Ain, const float* __restrict__ Wo3,
       const float* __restrict__ bo3, float* __restrict__ y) {
    __shared__ float Ws[LAG_ * H_];
    int tid = threadIdx.x;
    for (int i = tid; i < LAG_ * H_; i += 256) Ws[i] = Wo3[i];
    __syncthreads();
    int wrp = tid >> 5, lane = tid & 31;
    int row = blockIdx.x * 8 + wrp;
    const float* ar = Ain + (size_t)row * H_;
    float acc[LAG_] = {};
    for (int k = lane; k < H_; k += 32) {
        float a = ar[k];
#pragma unroll
        for (int o = 0; o < LAG_; o++) acc[o] = fmaf(a, Ws[o * H_ + k], acc[o]);
    }
#pragma unroll
    for (int o = 0; o < LAG_; o++) {
        float v = acc[o];
#pragma unroll
        for (int off = 16; off; off >>= 1) v += __shfl_xor_sync(0xffffffffu, v, off);
        if (lane == 0) y[(size_t)row * LAG_ + o] = v + bo3[o];
    }
}

// ============================== host ========================================
extern "C" void kernel_launch(void* const* d_in, const int* in_sizes, int n_in,
                              void* d_out, int out_size) {
    const float* x    = (const float*)d_in[0];
    const float* Wi1  = (const float*)d_in[1];  const float* bi1 = (const float*)d_in[2];
    const float* Wi2  = (const float*)d_in[3];  const float* bi2 = (const float*)d_in[4];
    const float* Wi3  = (const float*)d_in[5];  const float* bi3 = (const float*)d_in[6];
    const float* Wih0 = (const float*)d_in[7];  const float* Whh0 = (const float*)d_in[8];
    const float* bih0 = (const float*)d_in[9];  const float* bhh0 = (const float*)d_in[10];
    const float* Wih1 = (const float*)d_in[11]; const float* Whh1 = (const float*)d_in[12];
    const float* bih1 = (const float*)d_in[13]; const float* bhh1 = (const float*)d_in[14];
    const float* Wo1  = (const float*)d_in[15]; const float* bo1 = (const float*)d_in[16];
    const float* Wo2  = (const float*)d_in[17]; const float* bo2 = (const float*)d_in[18];
    const float* Wo3  = (const float*)d_in[19]; const float* bo3 = (const float*)d_in[20];
    float* y = (float*)d_out;

    cudaFuncSetAttribute(wm_gemm<0>, cudaFuncAttributeMaxDynamicSharedMemorySize, SMEM_SZ);
    cudaFuncSetAttribute(wm_gemm<3>, cudaFuncAttributeMaxDynamicSharedMemorySize, SMEM_SZ);
    cudaFuncSetAttribute(wm_gemm<4>, cudaFuncAttributeMaxDynamicSharedMemorySize, SMEM_SZ);
    cudaFuncSetAttribute(k_rnn,      cudaFuncAttributeMaxDynamicSharedMemorySize, RSMEM);

    float *A0, *bufB, *b0r;
    h16 *u, *v, *hsr;
    h16 *Wi2h, *Wi2l, *Wi3h, *Wi3l, *Wo1h, *Wo1l, *Wo2h, *Wo2l, *Wih0h, *Wih0l;
    cudaGetSymbolAddress((void**)&A0,   g_A0);
    cudaGetSymbolAddress((void**)&bufB, g_bufB);
    cudaGetSymbolAddress((void**)&b0r,  g_b0r);
    cudaGetSymbolAddress((void**)&u,    g_u);
    cudaGetSymbolAddress((void**)&v,    g_v);
    cudaGetSymbolAddress((void**)&hsr,  g_hsr);
    cudaGetSymbolAddress((void**)&Wi2h, g_Wi2_hi); cudaGetSymbolAddress((void**)&Wi2l, g_Wi2_lo);
    cudaGetSymbolAddress((void**)&Wi3h, g_Wi3_hi); cudaGetSymbolAddress((void**)&Wi3l, g_Wi3_lo);
    cudaGetSymbolAddress((void**)&Wo1h, g_Wo1_hi); cudaGetSymbolAddress((void**)&Wo1l, g_Wo1_lo);
    cudaGetSymbolAddress((void**)&Wo2h, g_Wo2_hi); cudaGetSymbolAddress((void**)&Wo2l, g_Wo2_lo);
    cudaGetSymbolAddress((void**)&Wih0h, g_Wih0_hi); cudaGetSymbolAddress((void**)&Wih0l, g_Wih0_lo);

    k_prep<<<512, 512>>>(Wi2, Wi3, Wo1, Wo2, Wih0, Whh0, bih0, bhh0,
                         Wih1, Whh1, bih1, bhh1);
    k_zero<<<512, 512>>>();

    // input MLP
    k_in1<<<NR_ / 64, 256>>>(x, Wi1, bi1);
    dim3 blk(256);
    dim3 gMLP(H_ / 128, NR_ / 128);              // (2, 1024)
    wm_gemm<3><<<gMLP, blk, SMEM_SZ>>>(u, Wi2h, Wi2l, bi2, v, nullptr, H_);
    wm_gemm<3><<<gMLP, blk, SMEM_SZ>>>(v, Wi3h, Wi3l, bi3, u, nullptr, H_);

    // hoisted layer-0 input projection: A0 = u @ Wih0r^T + b0r
    dim3 gA0(G_ / 128, NR_ / 128);               // (8, 1024)
    wm_gemm<0><<<gA0, blk, SMEM_SZ>>>(u, Wih0h, Wih0l, b0r, nullptr, A0, G_);

    // persistent balanced recurrence: 128 CTAs x 512 threads, 1 tile each,
    // both layers per step
    k_rnn<<<NCTA_STEP, 512, RSMEM>>>();

    // output MLP
    wm_gemm<3><<<gMLP, blk, SMEM_SZ>>>(hsr, Wo1h, Wo1l, bo1, v, nullptr, H_);
    wm_gemm<4><<<gMLP, blk, SMEM_SZ>>>(v, Wo2h, Wo2l, bo2, nullptr, bufB, H_);
    k_out3<<<NR_ / 8, 256>>>(bufB, Wo3, bo3, y);
}